// round 2
// baseline (speedup 1.0000x reference)
#include <cuda_runtime.h>
#include <cuda_bf16.h>
#include <cstdint>

// ===================== problem constants =====================
#define NTILES   1024      // 131072 rows / 128 rows per tile
#define GRID_X   148
#define NTHREADS 256       // 8 warps

// ===================== smem layout (bytes) =====================
// vectors
#define SM_BSUM   0        // b_in + bias        [128] f32
#define SM_BGATE  512      // b_gate             [128] f32
#define SM_SSIG   1024     // sigmoid(log_step)  [128] f32
#define SM_GAMMA  1536     // ln_gamma           [256] f32
#define SM_BETA   2560     // ln_beta            [256] f32
#define SM_PSUM   3584     // LN partial sums    [256] f32
#define SM_PSUM2  4608     // LN partial sumsq   [256] f32
// big tiles: [128 rows][256 cols] bf16, row stride 512B, XOR-swizzled 16B chunks
#define SM_A      6144
#define SM_W1     (SM_A  + 65536)   // [w_in | w_rec]
#define SM_W2     (SM_W1 + 65536)   // w_gate
#define SMEM_TOTAL (SM_W2 + 65536)  // 202752 bytes

// byte offset of bf16 element (r, c) in a [128][256] tile, swizzled
static __device__ __forceinline__ uint32_t toff(int r, int c) {
    uint32_t cc = ((uint32_t)c >> 3) ^ (((uint32_t)r & 7u) << 2);
    return ((uint32_t)r << 9) + (cc << 4) + (((uint32_t)c & 7u) << 1);
}

static __device__ __forceinline__ uint32_t smem_u32(const void* p) {
    uint32_t a;
    asm("{ .reg .u64 t; cvta.to.shared.u64 t, %1; cvt.u32.u64 %0, t; }" : "=r"(a) : "l"(p));
    return a;
}
static __device__ __forceinline__ float tanh_fast(float x) {
    float y; asm("tanh.approx.f32 %0, %1;" : "=f"(y) : "f"(x)); return y;
}
static __device__ __forceinline__ uint32_t packbf(float a, float b) {
    __nv_bfloat162 h = __floats2bfloat162_rn(a, b);
    return *reinterpret_cast<uint32_t*>(&h);
}
static __device__ __forceinline__ void ldsm4(uint32_t* r, uint32_t addr) {
    asm volatile("ldmatrix.sync.aligned.m8n8.x4.shared.b16 {%0,%1,%2,%3}, [%4];"
                 : "=r"(r[0]), "=r"(r[1]), "=r"(r[2]), "=r"(r[3]) : "r"(addr));
}
static __device__ __forceinline__ void mma16816(float* d, const uint32_t* a,
                                                uint32_t b0, uint32_t b1) {
    asm volatile(
        "mma.sync.aligned.m16n8k16.row.col.f32.bf16.bf16.f32 "
        "{%0,%1,%2,%3}, {%4,%5,%6,%7}, {%8,%9}, {%0,%1,%2,%3};"
        : "+f"(d[0]), "+f"(d[1]), "+f"(d[2]), "+f"(d[3])
        : "r"(a[0]), "r"(a[1]), "r"(a[2]), "r"(a[3]), "r"(b0), "r"(b1));
}

static __device__ __forceinline__ float epi_one(float dacc, float gacc, float bs,
                                                float bgv, float ssv, float sv) {
    float tgt   = tanh_fast(dacc + bs);
    float g     = __fdividef(1.f, 1.f + __expf(-(gacc + bgv)));
    float blend = fminf(ssv * g, 1.f);
    return sv + blend * (tgt - sv);
}

// ===================== kernel =====================
extern "C" __global__ void __launch_bounds__(NTHREADS, 1)
liquidcell_kernel(const float* __restrict__ x, const float* __restrict__ state,
                  const float* __restrict__ w_in, const float* __restrict__ b_in,
                  const float* __restrict__ w_rec, const float* __restrict__ w_gate,
                  const float* __restrict__ b_gate, const float* __restrict__ bias,
                  const float* __restrict__ log_step, const float* __restrict__ ln_g,
                  const float* __restrict__ ln_b, float* __restrict__ out) {
    extern __shared__ char smem[];
    const uint32_t sbase = smem_u32(smem);
    const int tid  = threadIdx.x;
    const int wid  = tid >> 5;
    const int lane = tid & 31;

    float* f_bsum  = (float*)(smem + SM_BSUM);
    float* f_bg    = (float*)(smem + SM_BGATE);
    float* f_ss    = (float*)(smem + SM_SSIG);
    float* f_gamma = (float*)(smem + SM_GAMMA);
    float* f_beta  = (float*)(smem + SM_BETA);
    float* f_ps    = (float*)(smem + SM_PSUM);
    float* f_ps2   = (float*)(smem + SM_PSUM2);

    // ---- one-time vectors ----
    if (tid < 128) {
        f_bsum[tid] = b_in[tid] + bias[tid];
        f_bg[tid]   = b_gate[tid];
        f_ss[tid]   = __fdividef(1.f, 1.f + __expf(-log_step[tid]));
    }
    f_gamma[tid] = ln_g[tid];
    f_beta[tid]  = ln_b[tid];

    // ---- one-time weights: fp32 -> bf16 swizzled smem ----
    // W1 = [w_in (cols 0..127) | w_rec (cols 128..255)]
    for (int i = tid; i < 4096; i += NTHREADS) {
        int row = i >> 5, c0 = (i & 31) << 2;
        float4 v = *(const float4*)(w_in + row * 128 + c0);
        uint2 p; p.x = packbf(v.x, v.y); p.y = packbf(v.z, v.w);
        *(uint2*)(smem + SM_W1 + toff(row, c0)) = p;
        v = *(const float4*)(w_rec + row * 128 + c0);
        p.x = packbf(v.x, v.y); p.y = packbf(v.z, v.w);
        *(uint2*)(smem + SM_W1 + toff(row, 128 + c0)) = p;
    }
    // W2 = w_gate, naturally [128][256]
    for (int i = tid; i < 8192; i += NTHREADS) {
        int row = i >> 6, c0 = (i & 63) << 2;
        float4 v = *(const float4*)(w_gate + row * 256 + c0);
        uint2 p; p.x = packbf(v.x, v.y); p.y = packbf(v.z, v.w);
        *(uint2*)(smem + SM_W2 + toff(row, c0)) = p;
    }
    __syncthreads();

    // ---- per-thread fragment addressing (warp tiling: 4 x 2) ----
    const int warp_m = wid & 3;        // 32-row strip
    const int warp_n = wid >> 2;       // 64-col strip
    // A ldmatrix roles: lanes 0-15 rows, lane>>4 selects k-half (+8 cols)
    uint32_t pA[2], swA[2];
#pragma unroll
    for (int i = 0; i < 2; i++) {
        int rowA = warp_m * 32 + i * 16 + (lane & 15);
        pA[i]  = (uint32_t)rowA << 9;
        swA[i] = ((uint32_t)rowA & 7u) << 2;
    }
    const uint32_t hiA = (uint32_t)(lane >> 4);           // 0/1 -> chunk +0/+1
    // B ldmatrix roles: pairs of n8 frags
    uint32_t pB[4], swB[4];
#pragma unroll
    for (int p = 0; p < 4; p++) {
        int rowB = warp_n * 64 + p * 16 + ((lane >> 4) << 3) + (lane & 7);
        pB[p]  = (uint32_t)rowB << 9;
        swB[p] = ((uint32_t)rowB & 7u) << 2;
    }
    const uint32_t hiB = (uint32_t)((lane >> 3) & 1);

    const uint32_t aA  = sbase + SM_A;
    const uint32_t aW1 = sbase + SM_W1;
    const uint32_t aW2 = sbase + SM_W2;

    const int part = tid >> 7;    // 0: x half, 1: state half
    const int r    = tid & 127;   // tile row owned in pass1/pass2

    for (int tile = blockIdx.x; tile < NTILES; tile += gridDim.x) {
        const int rowg = (tile << 7) + r;
        const float* srcrow = part ? (state + rowg * 128) : (x + rowg * 128);

        // ---- pass1: bf16(x) | bf16(tanh(state)) into A, LN partial stats ----
        float s = 0.f, s2 = 0.f;
#pragma unroll
        for (int c0 = 0; c0 < 128; c0 += 4) {
            float4 v = *(const float4*)(srcrow + c0);
            s  += (v.x + v.y) + (v.z + v.w);
            s2 += (v.x * v.x + v.y * v.y) + (v.z * v.z + v.w * v.w);
            if (part) {
                v.x = tanh_fast(v.x); v.y = tanh_fast(v.y);
                v.z = tanh_fast(v.z); v.w = tanh_fast(v.w);
            }
            uint2 pk; pk.x = packbf(v.x, v.y); pk.y = packbf(v.z, v.w);
            *(uint2*)(smem + SM_A + toff(r, part * 128 + c0)) = pk;
        }
        f_ps[tid]  = s;
        f_ps2[tid] = s2;
        __syncthreads();

        // ---- GEMM1: drive accumulators (regs), A x W1, K=256 ----
        float accD[2][8][4];
#pragma unroll
        for (int i = 0; i < 2; i++)
#pragma unroll
            for (int j = 0; j < 8; j++)
#pragma unroll
                for (int q = 0; q < 4; q++) accD[i][j][q] = 0.f;
#pragma unroll
        for (int ks = 0; ks < 16; ks++) {
            uint32_t a[2][4], b[4][4];
            const uint32_t ckA = 2u * ks + hiA;
            const uint32_t ckB = 2u * ks + hiB;
#pragma unroll
            for (int i = 0; i < 2; i++) ldsm4(a[i], aA + pA[i] + ((ckA ^ swA[i]) << 4));
#pragma unroll
            for (int p = 0; p < 4; p++) ldsm4(b[p], aW1 + pB[p] + ((ckB ^ swB[p]) << 4));
#pragma unroll
            for (int p = 0; p < 4; p++)
#pragma unroll
                for (int i = 0; i < 2; i++) {
                    mma16816(accD[i][2 * p],     a[i], b[p][0], b[p][1]);
                    mma16816(accD[i][2 * p + 1], a[i], b[p][2], b[p][3]);
                }
        }
        __syncthreads();   // all warps done reading A before overwrite

        // ---- pass2: LayerNorm (fp32 re-read from global, L2-hit) -> A ----
        {
            float ts   = f_ps[r] + f_ps[r + 128];
            float ts2  = f_ps2[r] + f_ps2[r + 128];
            float mu   = ts * (1.f / 256.f);
            float var  = fmaf(-mu, mu, ts2 * (1.f / 256.f));
            float rstd = rsqrtf(var + 1e-5f);
            const float* gp = f_gamma + part * 128;
            const float* bp = f_beta  + part * 128;
#pragma unroll
            for (int c0 = 0; c0 < 128; c0 += 4) {
                float4 v = *(const float4*)(srcrow + c0);
                float4 n;
                n.x = fmaf((v.x - mu) * rstd, gp[c0 + 0], bp[c0 + 0]);
                n.y = fmaf((v.y - mu) * rstd, gp[c0 + 1], bp[c0 + 1]);
                n.z = fmaf((v.z - mu) * rstd, gp[c0 + 2], bp[c0 + 2]);
                n.w = fmaf((v.w - mu) * rstd, gp[c0 + 3], bp[c0 + 3]);
                uint2 pk; pk.x = packbf(n.x, n.y); pk.y = packbf(n.z, n.w);
                *(uint2*)(smem + SM_A + toff(r, part * 128 + c0)) = pk;
            }
        }
        __syncthreads();

        // ---- GEMM2: gate accumulators, A x W2, K=256 ----
        float accG[2][8][4];
#pragma unroll
        for (int i = 0; i < 2; i++)
#pragma unroll
            for (int j = 0; j < 8; j++)
#pragma unroll
                for (int q = 0; q < 4; q++) accG[i][j][q] = 0.f;
#pragma unroll
        for (int ks = 0; ks < 16; ks++) {
            uint32_t a[2][4], b[4][4];
            const uint32_t ckA = 2u * ks + hiA;
            const uint32_t ckB = 2u * ks + hiB;
#pragma unroll
            for (int i = 0; i < 2; i++) ldsm4(a[i], aA + pA[i] + ((ckA ^ swA[i]) << 4));
#pragma unroll
            for (int p = 0; p < 4; p++) ldsm4(b[p], aW2 + pB[p] + ((ckB ^ swB[p]) << 4));
#pragma unroll
            for (int p = 0; p < 4; p++)
#pragma unroll
                for (int i = 0; i < 2; i++) {
                    mma16816(accG[i][2 * p],     a[i], b[p][0], b[p][1]);
                    mma16816(accG[i][2 * p + 1], a[i], b[p][2], b[p][3]);
                }
        }

        // ---- epilogue: fused tanh/sigmoid/blend, write out ----
        {
            const int rbase = (tile << 7) + warp_m * 32 + (lane >> 2);
            const int cbase = warp_n * 64 + ((lane & 3) << 1);
#pragma unroll
            for (int i = 0; i < 2; i++) {
#pragma unroll
                for (int j = 0; j < 8; j++) {
                    const int c  = cbase + j * 8;
                    const int r0 = rbase + i * 16;
                    const int r1 = r0 + 8;
                    const float bs0 = f_bsum[c], bs1 = f_bsum[c + 1];
                    const float bg0 = f_bg[c],   bg1 = f_bg[c + 1];
                    const float ss0 = f_ss[c],   ss1 = f_ss[c + 1];
                    float2 sv0 = *(const float2*)(state + r0 * 128 + c);
                    float2 sv1 = *(const float2*)(state + r1 * 128 + c);
                    float2 o0, o1;
                    o0.x = epi_one(accD[i][j][0], accG[i][j][0], bs0, bg0, ss0, sv0.x);
                    o0.y = epi_one(accD[i][j][1], accG[i][j][1], bs1, bg1, ss1, sv0.y);
                    o1.x = epi_one(accD[i][j][2], accG[i][j][2], bs0, bg0, ss0, sv1.x);
                    o1.y = epi_one(accD[i][j][3], accG[i][j][3], bs1, bg1, ss1, sv1.y);
                    *(float2*)(out + r0 * 128 + c) = o0;
                    *(float2*)(out + r1 * 128 + c) = o1;
                }
            }
        }
        __syncthreads();   // A + stats reuse guard for next tile
    }
}

// ===================== launch =====================
extern "C" void kernel_launch(void* const* d_in, const int* in_sizes, int n_in,
                              void* d_out, int out_size) {
    const float* x        = (const float*)d_in[0];
    const float* state    = (const float*)d_in[1];
    const float* w_in     = (const float*)d_in[2];
    const float* b_in     = (const float*)d_in[3];
    const float* w_rec    = (const float*)d_in[4];
    const float* w_gate   = (const float*)d_in[5];
    const float* b_gate   = (const float*)d_in[6];
    const float* bias     = (const float*)d_in[7];
    const float* log_step = (const float*)d_in[8];
    const float* ln_g     = (const float*)d_in[9];
    const float* ln_b     = (const float*)d_in[10];
    float* out = (float*)d_out;

    static int attr_done = 0;
    if (!attr_done) {
        cudaFuncSetAttribute(liquidcell_kernel,
                             cudaFuncAttributeMaxDynamicSharedMemorySize, SMEM_TOTAL);
        attr_done = 1;
    }
    liquidcell_kernel<<<GRID_X, NTHREADS, SMEM_TOTAL>>>(
        x, state, w_in, b_in, w_rec, w_gate, b_gate, bias, log_step, ln_g, ln_b, out);
}

// round 3
// speedup vs baseline: 1.2081x; 1.2081x over previous
#include <cuda_runtime.h>
#include <cuda_bf16.h>
#include <cstdint>

// ===================== problem constants =====================
#define NTILES   1024      // 131072 rows / 128 rows per tile
#define GRID_X   148
#define NTHREADS 512       // 16 warps

// ===================== smem layout (bytes) =====================
#define SM_BSUM   0        // b_in + bias                 [128] f32
#define SM_BGP    512      // b_gate + c2 (beta fold)     [128] f32
#define SM_SS     1024     // sigmoid(log_step)           [128] f32
#define SM_C1     1536     // sum_k gamma_k w_gate[h,k]   [128] f32
#define SM_RSTD   2048     // per-row rstd                [128] f32
#define SM_MURSTD 2560     // per-row mu*rstd             [128] f32
#define SM_AX     4096     // bf16(x)        [128][128], 256B rows, swizzled (32KB)
#define SM_AS     36864    // bf16(state) -> bf16(tanh)   (32KB)
#define SM_W1     69632    // [w_in | w_rec]  [128][256] bf16 swizzled (64KB)
#define SM_W2     135168   // gamma .* w_gate [128][256] bf16 swizzled (64KB)
#define SMEM_TOTAL 200704

// swizzled byte offset in a [128][256] bf16 tile (512B row stride)
static __device__ __forceinline__ uint32_t toff512(int r, int c) {
    uint32_t cc = ((uint32_t)c >> 3) ^ (((uint32_t)r & 7u) << 2);
    return ((uint32_t)r << 9) + (cc << 4) + (((uint32_t)c & 7u) << 1);
}
// swizzled byte offset in a [128][128] bf16 tile (256B row stride)
static __device__ __forceinline__ uint32_t toff128(int r, int c) {
    uint32_t cc = (((uint32_t)c >> 3) ^ (((uint32_t)r & 7u) << 1)) & 15u;
    return ((uint32_t)r << 8) + (cc << 4) + (((uint32_t)c & 7u) << 1);
}

static __device__ __forceinline__ uint32_t smem_u32(const void* p) {
    uint32_t a;
    asm("{ .reg .u64 t; cvta.to.shared.u64 t, %1; cvt.u32.u64 %0, t; }" : "=r"(a) : "l"(p));
    return a;
}
static __device__ __forceinline__ float tanh_fast(float x) {
    float y; asm("tanh.approx.f32 %0, %1;" : "=f"(y) : "f"(x)); return y;
}
static __device__ __forceinline__ uint32_t packbf(float a, float b) {
    __nv_bfloat162 h = __floats2bfloat162_rn(a, b);
    return *reinterpret_cast<uint32_t*>(&h);
}
static __device__ __forceinline__ void ldsm4(uint32_t* r, uint32_t addr) {
    asm volatile("ldmatrix.sync.aligned.m8n8.x4.shared.b16 {%0,%1,%2,%3}, [%4];"
                 : "=r"(r[0]), "=r"(r[1]), "=r"(r[2]), "=r"(r[3]) : "r"(addr));
}
static __device__ __forceinline__ void mma16816(float* d, const uint32_t* a,
                                                uint32_t b0, uint32_t b1) {
    asm volatile(
        "mma.sync.aligned.m16n8k16.row.col.f32.bf16.bf16.f32 "
        "{%0,%1,%2,%3}, {%4,%5,%6,%7}, {%8,%9}, {%0,%1,%2,%3};"
        : "+f"(d[0]), "+f"(d[1]), "+f"(d[2]), "+f"(d[3])
        : "r"(a[0]), "r"(a[1]), "r"(a[2]), "r"(a[3]), "r"(b0), "r"(b1));
}

static __device__ __forceinline__ float epi_one(float drive_pre, float gate_pre,
                                                float ssv, float sv) {
    float tgt   = tanh_fast(drive_pre);
    float g     = __fdividef(1.f, 1.f + __expf(-gate_pre));
    float blend = fminf(ssv * g, 1.f);
    return sv + blend * (tgt - sv);
}

// One K=256 GEMM: A = [Ax | As] (two 128x128 swizzled bf16 buffers), B = W tile.
static __device__ __forceinline__ void run_gemm(
    float acc[2][4][4], uint32_t aAx, uint32_t aAs, uint32_t wb,
    const uint32_t* offA, const uint32_t* swA, uint32_t hiA,
    const uint32_t* offB, const uint32_t* swB, uint32_t hiB)
{
#pragma unroll
    for (int ks = 0; ks < 16; ks++) {
        const uint32_t ab  = (ks < 8) ? aAx : aAs;
        const uint32_t ckA = (uint32_t)((ks & 7) << 1) + hiA;
        const uint32_t ckB = (uint32_t)(ks << 1) + hiB;
        uint32_t a[2][4], b[2][4];
#pragma unroll
        for (int i = 0; i < 2; i++) ldsm4(a[i], ab + offA[i] + ((ckA ^ swA[i]) << 4));
#pragma unroll
        for (int p = 0; p < 2; p++) ldsm4(b[p], wb + offB[p] + ((ckB ^ swB[p]) << 4));
#pragma unroll
        for (int p = 0; p < 2; p++)
#pragma unroll
            for (int i = 0; i < 2; i++) {
                mma16816(acc[i][2 * p],     a[i], b[p][0], b[p][1]);
                mma16816(acc[i][2 * p + 1], a[i], b[p][2], b[p][3]);
            }
    }
}

// ===================== kernel =====================
extern "C" __global__ void __launch_bounds__(NTHREADS, 1)
liquidcell_kernel(const float* __restrict__ x, const float* __restrict__ state,
                  const float* __restrict__ w_in, const float* __restrict__ b_in,
                  const float* __restrict__ w_rec, const float* __restrict__ w_gate,
                  const float* __restrict__ b_gate, const float* __restrict__ bias,
                  const float* __restrict__ log_step, const float* __restrict__ ln_g,
                  const float* __restrict__ ln_b, float* __restrict__ out) {
    extern __shared__ char smem[];
    const uint32_t sbase = smem_u32(smem);
    const int tid  = threadIdx.x;
    const int wid  = tid >> 5;
    const int lane = tid & 31;

    float* f_bsum = (float*)(smem + SM_BSUM);
    float* f_bgp  = (float*)(smem + SM_BGP);
    float* f_ss   = (float*)(smem + SM_SS);
    float* f_c1   = (float*)(smem + SM_C1);
    float* f_rstd = (float*)(smem + SM_RSTD);
    float* f_mrs  = (float*)(smem + SM_MURSTD);

    // ---- one-time: fold LN gamma/beta into W2 / c1 / bgp ----
    if (tid < 128) {
        float c1 = 0.f, c2 = 0.f;
        const float* wr = w_gate + tid * 256;
        for (int k = 0; k < 256; k++) {
            float wv = wr[k];
            c1 = fmaf(ln_g[k], wv, c1);
            c2 = fmaf(ln_b[k], wv, c2);
        }
        f_c1[tid]   = c1;
        f_bgp[tid]  = b_gate[tid] + c2;
        f_bsum[tid] = b_in[tid] + bias[tid];
        f_ss[tid]   = __fdividef(1.f, 1.f + __expf(-log_step[tid]));
    }
    // W1 = [w_in | w_rec], bf16, swizzled (512B rows)
    for (int i = tid; i < 8192; i += NTHREADS) {
        int row = i >> 6, c0 = (i & 63) << 2;
        float4 v = (c0 < 128) ? *(const float4*)(w_in + row * 128 + c0)
                              : *(const float4*)(w_rec + row * 128 + (c0 - 128));
        uint2 p; p.x = packbf(v.x, v.y); p.y = packbf(v.z, v.w);
        *(uint2*)(smem + SM_W1 + toff512(row, c0)) = p;
    }
    // W2 = gamma .* w_gate, bf16, swizzled
    for (int i = tid; i < 8192; i += NTHREADS) {
        int row = i >> 6, c0 = (i & 63) << 2;
        float4 v = *(const float4*)(w_gate + row * 256 + c0);
        float4 g = *(const float4*)(ln_g + c0);
        v.x *= g.x; v.y *= g.y; v.z *= g.z; v.w *= g.w;
        uint2 p; p.x = packbf(v.x, v.y); p.y = packbf(v.z, v.w);
        *(uint2*)(smem + SM_W2 + toff512(row, c0)) = p;
    }
    __syncthreads();

    // ---- per-warp fragment addressing (4 warps_m x 4 warps_n, 32x32 tiles) ----
    const int warp_m = wid & 3;
    const int warp_n = wid >> 2;
    uint32_t offA[2], swA[2];
#pragma unroll
    for (int i = 0; i < 2; i++) {
        int rowA = warp_m * 32 + i * 16 + (lane & 15);
        offA[i] = (uint32_t)rowA << 8;
        swA[i]  = ((uint32_t)rowA & 7u) << 1;
    }
    const uint32_t hiA = (uint32_t)(lane >> 4);
    uint32_t offB[2], swB[2];
#pragma unroll
    for (int p = 0; p < 2; p++) {
        int rowB = warp_n * 32 + p * 16 + ((lane >> 4) << 3) + (lane & 7);
        offB[p] = (uint32_t)rowB << 9;
        swB[p]  = ((uint32_t)rowB & 7u) << 2;
    }
    const uint32_t hiB = (uint32_t)((lane >> 3) & 1);

    const uint32_t aAx = sbase + SM_AX;
    const uint32_t aAs = sbase + SM_AS;
    const uint32_t aW1 = sbase + SM_W1;
    const uint32_t aW2 = sbase + SM_W2;

    for (int tile = blockIdx.x; tile < NTILES; tile += gridDim.x) {
        const int tb = tile << 7;   // first global row of tile

        // ---- pass1: coalesced load, bf16ize, warp-reduced LN stats ----
        float myS = 0.f, myS2 = 0.f;   // lane<8 owns row (lane*16 + wid)
#pragma unroll
        for (int s = 0; s < 8; s++) {
            const int r = s * 16 + wid;
            float4 v = *(const float4*)(x + (size_t)(tb + r) * 128 + lane * 4);
            float ls  = (v.x + v.y) + (v.z + v.w);
            float ls2 = (v.x * v.x + v.y * v.y) + (v.z * v.z + v.w * v.w);
#pragma unroll
            for (int o = 16; o; o >>= 1) {
                ls  += __shfl_xor_sync(0xffffffffu, ls,  o);
                ls2 += __shfl_xor_sync(0xffffffffu, ls2, o);
            }
            if (lane == s) { myS = ls; myS2 = ls2; }
            uint2 p; p.x = packbf(v.x, v.y); p.y = packbf(v.z, v.w);
            *(uint2*)(smem + SM_AX + toff128(r, lane * 4)) = p;
        }
#pragma unroll
        for (int s = 0; s < 8; s++) {
            const int r = s * 16 + wid;
            float4 v = *(const float4*)(state + (size_t)(tb + r) * 128 + lane * 4);
            float ls  = (v.x + v.y) + (v.z + v.w);
            float ls2 = (v.x * v.x + v.y * v.y) + (v.z * v.z + v.w * v.w);
#pragma unroll
            for (int o = 16; o; o >>= 1) {
                ls  += __shfl_xor_sync(0xffffffffu, ls,  o);
                ls2 += __shfl_xor_sync(0xffffffffu, ls2, o);
            }
            if (lane == s) { myS += ls; myS2 += ls2; }
            uint2 p; p.x = packbf(v.x, v.y); p.y = packbf(v.z, v.w);
            *(uint2*)(smem + SM_AS + toff128(r, lane * 4)) = p;
        }
        if (lane < 8) {
            const int r = lane * 16 + wid;
            float mu   = myS * (1.f / 256.f);
            float var  = fmaf(-mu, mu, myS2 * (1.f / 256.f));
            float rstd = rsqrtf(var + 1e-5f);
            f_rstd[r] = rstd;
            f_mrs[r]  = mu * rstd;
        }
        __syncthreads();

        // ---- GEMM2 first (needs RAW state): G = [x|state] @ W2' ----
        float accG[2][4][4];
#pragma unroll
        for (int i = 0; i < 2; i++)
#pragma unroll
            for (int j = 0; j < 4; j++)
#pragma unroll
                for (int q = 0; q < 4; q++) accG[i][j][q] = 0.f;
        run_gemm(accG, aAx, aAs, aW2, offA, swA, hiA, offB, swB, hiB);
        __syncthreads();

        // ---- in-place tanh on state buffer (smem only) ----
        {
            uint32_t* p = (uint32_t*)(smem + SM_AS);
#pragma unroll
            for (int k = 0; k < 16; k++) {
                uint32_t v = p[tid + k * NTHREADS];
                __nv_bfloat162 h = *reinterpret_cast<__nv_bfloat162*>(&v);
                float2 f = __bfloat1622float2(h);
                p[tid + k * NTHREADS] = packbf(tanh_fast(f.x), tanh_fast(f.y));
            }
        }
        __syncthreads();

        // ---- GEMM1: D = [x|tanh(state)] @ W1 ----
        float accD[2][4][4];
#pragma unroll
        for (int i = 0; i < 2; i++)
#pragma unroll
            for (int j = 0; j < 4; j++)
#pragma unroll
                for (int q = 0; q < 4; q++) accD[i][j][q] = 0.f;
        run_gemm(accD, aAx, aAs, aW1, offA, swA, hiA, offB, swB, hiB);

        // ---- fused epilogue ----
        {
            const int lrb = warp_m * 32 + (lane >> 2);
            const int cb  = warp_n * 32 + ((lane & 3) << 1);
#pragma unroll
            for (int i = 0; i < 2; i++) {
                const int lr0 = lrb + i * 16, lr1 = lr0 + 8;
                const float rs0 = f_rstd[lr0], mr0 = f_mrs[lr0];
                const float rs1 = f_rstd[lr1], mr1 = f_mrs[lr1];
                const float* sp0 = state + (size_t)(tb + lr0) * 128;
                const float* sp1 = state + (size_t)(tb + lr1) * 128;
                float* op0 = out + (size_t)(tb + lr0) * 128;
                float* op1 = out + (size_t)(tb + lr1) * 128;
#pragma unroll
                for (int j = 0; j < 4; j++) {
                    const int c = cb + j * 8;
                    const float bs0 = f_bsum[c], bs1 = f_bsum[c + 1];
                    const float bg0 = f_bgp[c],  bg1 = f_bgp[c + 1];
                    const float c10 = f_c1[c],   c11 = f_c1[c + 1];
                    const float ss0 = f_ss[c],   ss1 = f_ss[c + 1];
                    float2 sv0 = *(const float2*)(sp0 + c);
                    float2 sv1 = *(const float2*)(sp1 + c);
                    float2 o0, o1;
                    o0.x = epi_one(accD[i][j][0] + bs0,
                                   fmaf(rs0, accG[i][j][0], fmaf(-mr0, c10, bg0)), ss0, sv0.x);
                    o0.y = epi_one(accD[i][j][1] + bs1,
                                   fmaf(rs0, accG[i][j][1], fmaf(-mr0, c11, bg1)), ss1, sv0.y);
                    o1.x = epi_one(accD[i][j][2] + bs0,
                                   fmaf(rs1, accG[i][j][2], fmaf(-mr1, c10, bg0)), ss0, sv1.x);
                    o1.y = epi_one(accD[i][j][3] + bs1,
                                   fmaf(rs1, accG[i][j][3], fmaf(-mr1, c11, bg1)), ss1, sv1.y);
                    *(float2*)(op0 + c) = o0;
                    *(float2*)(op1 + c) = o1;
                }
            }
        }
        __syncthreads();   // A buffers / stats reuse guard for next tile
    }
}

// ===================== launch =====================
extern "C" void kernel_launch(void* const* d_in, const int* in_sizes, int n_in,
                              void* d_out, int out_size) {
    const float* x        = (const float*)d_in[0];
    const float* state    = (const float*)d_in[1];
    const float* w_in     = (const float*)d_in[2];
    const float* b_in     = (const float*)d_in[3];
    const float* w_rec    = (const float*)d_in[4];
    const float* w_gate   = (const float*)d_in[5];
    const float* b_gate   = (const float*)d_in[6];
    const float* bias     = (const float*)d_in[7];
    const float* log_step = (const float*)d_in[8];
    const float* ln_g     = (const float*)d_in[9];
    const float* ln_b     = (const float*)d_in[10];
    float* out = (float*)d_out;

    static int attr_done = 0;
    if (!attr_done) {
        cudaFuncSetAttribute(liquidcell_kernel,
                             cudaFuncAttributeMaxDynamicSharedMemorySize, SMEM_TOTAL);
        attr_done = 1;
    }
    liquidcell_kernel<<<GRID_X, NTHREADS, SMEM_TOTAL>>>(
        x, state, w_in, b_in, w_rec, w_gate, b_gate, bias, log_step, ln_g, ln_b, out);
}